// round 2
// baseline (speedup 1.0000x reference)
#include <cuda_runtime.h>
#include <math.h>

#define NUM_E   8
#define DIM     1024
#define HID     4096
#define TOKENS  8192          // B*S
#define CAP     TOKENS        // max rows per expert (top-2 of distinct experts)
#define ROWS_T  (TOKENS * 2)  // total (token, slot) rows

// Scratch (device globals: allocation-free per harness rules)
static __device__ float g_h[(size_t)ROWS_T * HID];   // 268 MB fc1 activations
static __device__ float g_y[(size_t)ROWS_T * DIM];   // 64 MB fc2 outputs per slot
static __device__ int   g_rowmap[NUM_E * CAP];       // rowmap[e*CAP+pos] = t*2+slot
static __device__ int   g_cnt[NUM_E];
static __device__ float g_topw[ROWS_T];              // weight per (t, slot)

// ---------------------------------------------------------------- utilities
__device__ __forceinline__ unsigned long long pk2(float f) {
    unsigned long long r;
    unsigned int u = __float_as_uint(f);
    asm("mov.b64 %0, {%1, %1};" : "=l"(r) : "r"(u));
    return r;
}
__device__ __forceinline__ void ffma2(unsigned long long& d,
                                      unsigned long long a,
                                      unsigned long long b) {
    // packed f32x2 FMA (sm_103a FFMA2 pipe): d = a*b + d elementwise
    asm("fma.rn.f32x2 %0, %1, %2, %0;" : "+l"(d) : "l"(a), "l"(b));
}
__device__ __forceinline__ float gelu_exact(float v) {
    return 0.5f * v * (1.0f + erff(v * 0.7071067811865476f));
}

// ---------------------------------------------------------------- router
__global__ void zero_cnt_kernel() {
    if (threadIdx.x < NUM_E) g_cnt[threadIdx.x] = 0;
}

__global__ __launch_bounds__(256) void router_kernel(
    const float* __restrict__ x, const float* __restrict__ Wr) {
    const int t = blockIdx.x;
    const int tid = threadIdx.x;

    // each thread covers 4 contiguous d values (256*4 = 1024)
    const float4 xv = *(const float4*)(x + (size_t)t * DIM + tid * 4);
    float acc[NUM_E];
#pragma unroll
    for (int e = 0; e < NUM_E; e++) {
        const float4 wv = *(const float4*)(Wr + e * DIM + tid * 4);
        acc[e] = xv.x * wv.x + xv.y * wv.y + xv.z * wv.z + xv.w * wv.w;
    }
#pragma unroll
    for (int off = 16; off; off >>= 1)
#pragma unroll
        for (int e = 0; e < NUM_E; e++)
            acc[e] += __shfl_down_sync(0xffffffffu, acc[e], off);

    __shared__ float sred[8][NUM_E];
    const int wid = tid >> 5, lane = tid & 31;
    if (lane == 0) {
#pragma unroll
        for (int e = 0; e < NUM_E; e++) sred[wid][e] = acc[e];
    }
    __syncthreads();

    if (tid == 0) {
        float lg[NUM_E];
#pragma unroll
        for (int e = 0; e < NUM_E; e++) {
            float s = 0.f;
#pragma unroll
            for (int w = 0; w < 8; w++) s += sred[w][e];
            lg[e] = s;
        }
        float mx = lg[0];
#pragma unroll
        for (int e = 1; e < NUM_E; e++) mx = fmaxf(mx, lg[e]);
        float p[NUM_E], psum = 0.f;
#pragma unroll
        for (int e = 0; e < NUM_E; e++) { p[e] = expf(lg[e] - mx); psum += p[e]; }
        const float inv = 1.0f / psum;
#pragma unroll
        for (int e = 0; e < NUM_E; e++) p[e] *= inv;

        // top-2, first occurrence on ties (matches lax.top_k)
        int i1 = 0;
#pragma unroll
        for (int e = 1; e < NUM_E; e++) if (p[e] > p[i1]) i1 = e;
        int i2 = (i1 == 0) ? 1 : 0;
#pragma unroll
        for (int e = 0; e < NUM_E; e++)
            if (e != i1 && p[e] > p[i2]) i2 = e;
        // enforce first-occurrence among non-i1 entries
        {
            int best = -1;
#pragma unroll
            for (int e = 0; e < NUM_E; e++) {
                if (e == i1) continue;
                if (best < 0 || p[e] > p[best]) best = e;
            }
            i2 = best;
        }

        int p1 = atomicAdd(&g_cnt[i1], 1);
        g_rowmap[i1 * CAP + p1] = t * 2;
        int p2 = atomicAdd(&g_cnt[i2], 1);
        g_rowmap[i2 * CAP + p2] = t * 2 + 1;
        g_topw[t * 2]     = p[i1];
        g_topw[t * 2 + 1] = p[i2];
    }
}

// ---------------------------------------------------------------- grouped GEMM
// C[r, n0+j] = act( sum_k A[arow, k] * Bw[e, k, n0+j] + bias[e, n0+j] )
// 128x128x16 tile, 256 threads, 8x8 per-thread micro-tile on the f32x2 pipe.
template <bool DO_GELU, bool GATHER_TOK>
__device__ __forceinline__ void gemm_body(
    const float* __restrict__ A, const float* __restrict__ Bw,
    const float* __restrict__ bias, float* __restrict__ C,
    const int Kdim, const int Ndim) {
    const int e = blockIdx.z;
    const int cnt = g_cnt[e];
    const int m0 = blockIdx.x * 128;
    if (m0 >= cnt) return;
    const int n0 = blockIdx.y * 128;
    const int tid = threadIdx.x;
    const int tx = tid & 15, ty = tid >> 4;

    __shared__ float As[16][132];  // transposed, padded (16B-aligned rows)
    __shared__ float Bs[16][128];

    const float* Be = Bw + (size_t)e * Kdim * Ndim;

    // A loader: 512 float4 slots over (m=128, k4=4); this thread owns slots tid, tid+256
    const int ma0 = tid >> 2;            // 0..63 (second row = ma0+64)
    const int ka4 = (tid & 3) * 4;
    const int gm0 = m0 + ma0, gm1 = gm0 + 64;
    const int r0 = (gm0 < cnt) ? g_rowmap[e * CAP + gm0] : 0;
    const int r1 = (gm1 < cnt) ? g_rowmap[e * CAP + gm1] : 0;
    const float* pa0 = A + (size_t)(GATHER_TOK ? (r0 >> 1) : r0) * Kdim + ka4;
    const float* pa1 = A + (size_t)(GATHER_TOK ? (r1 >> 1) : r1) * Kdim + ka4;

    // B loader: 512 float4 slots over (k=16, n4=32)
    const int kb = tid >> 5;             // 0..7 (second row = kb+8)
    const int nb = (tid & 31) * 4;
    const float* pb = Be + (size_t)kb * Ndim + n0 + nb;

    unsigned long long acc[8][4];
#pragma unroll
    for (int i = 0; i < 8; i++)
#pragma unroll
        for (int j = 0; j < 4; j++) acc[i][j] = 0ull;

    const int KT = Kdim >> 4;
    for (int kt = 0; kt < KT; kt++) {
        const float4 a0 = *(const float4*)(pa0 + kt * 16);
        const float4 a1 = *(const float4*)(pa1 + kt * 16);
        const float4 b0 = *(const float4*)(pb + (size_t)kt * 16 * Ndim);
        const float4 b1 = *(const float4*)(pb + (size_t)(kt * 16 + 8) * Ndim);
        __syncthreads();
        As[ka4 + 0][ma0] = a0.x; As[ka4 + 1][ma0] = a0.y;
        As[ka4 + 2][ma0] = a0.z; As[ka4 + 3][ma0] = a0.w;
        As[ka4 + 0][ma0 + 64] = a1.x; As[ka4 + 1][ma0 + 64] = a1.y;
        As[ka4 + 2][ma0 + 64] = a1.z; As[ka4 + 3][ma0 + 64] = a1.w;
        *(float4*)&Bs[kb][nb] = b0;
        *(float4*)&Bs[kb + 8][nb] = b1;
        __syncthreads();
#pragma unroll
        for (int kk = 0; kk < 16; kk++) {
            const float4 af0 = *(const float4*)&As[kk][ty * 8];
            const float4 af1 = *(const float4*)&As[kk][ty * 8 + 4];
            const ulonglong2 bp0 = *(const ulonglong2*)&Bs[kk][tx * 8];
            const ulonglong2 bp1 = *(const ulonglong2*)&Bs[kk][tx * 8 + 4];
            unsigned long long ar[8];
            ar[0] = pk2(af0.x); ar[1] = pk2(af0.y);
            ar[2] = pk2(af0.z); ar[3] = pk2(af0.w);
            ar[4] = pk2(af1.x); ar[5] = pk2(af1.y);
            ar[6] = pk2(af1.z); ar[7] = pk2(af1.w);
            const unsigned long long bp[4] = {bp0.x, bp0.y, bp1.x, bp1.y};
#pragma unroll
            for (int i = 0; i < 8; i++)
#pragma unroll
                for (int j = 0; j < 4; j++) ffma2(acc[i][j], ar[i], bp[j]);
        }
    }

    // epilogue
    float bv[8];
#pragma unroll
    for (int j = 0; j < 8; j++) bv[j] = bias[e * Ndim + n0 + tx * 8 + j];

#pragma unroll
    for (int i = 0; i < 8; i++) {
        const int gm = m0 + ty * 8 + i;
        if (gm >= cnt) continue;
        const int r = g_rowmap[e * CAP + gm];
        float* pc = C + (size_t)r * Ndim + n0 + tx * 8;
        float out[8];
#pragma unroll
        for (int j = 0; j < 4; j++) {
            const unsigned long long v = acc[i][j];
            float lo = __uint_as_float((unsigned int)v) + bv[2 * j];
            float hi = __uint_as_float((unsigned int)(v >> 32)) + bv[2 * j + 1];
            if (DO_GELU) { lo = gelu_exact(lo); hi = gelu_exact(hi); }
            out[2 * j] = lo; out[2 * j + 1] = hi;
        }
        *(float4*)pc       = make_float4(out[0], out[1], out[2], out[3]);
        *(float4*)(pc + 4) = make_float4(out[4], out[5], out[6], out[7]);
    }
}

__global__ __launch_bounds__(256, 2) void fc1_kernel(
    const float* __restrict__ x, const float* __restrict__ W1,
    const float* __restrict__ b1) {
    gemm_body<true, true>(x, W1, b1, g_h, DIM, HID);
}

__global__ __launch_bounds__(256, 2) void fc2_kernel(
    const float* __restrict__ W2, const float* __restrict__ b2) {
    gemm_body<false, false>(g_h, W2, b2, g_y, HID, DIM);
}

// ---------------------------------------------------------------- combine
__global__ __launch_bounds__(256) void combine_kernel(float* __restrict__ out) {
    const int t = blockIdx.x;
    const int d = threadIdx.x * 4;
    const float w0 = g_topw[2 * t];
    const float w1 = g_topw[2 * t + 1];
    const float4 y0 = *(const float4*)&g_y[(size_t)(2 * t) * DIM + d];
    const float4 y1 = *(const float4*)&g_y[(size_t)(2 * t + 1) * DIM + d];
    float4 o;
    o.x = w0 * y0.x + w1 * y1.x;
    o.y = w0 * y0.y + w1 * y1.y;
    o.z = w0 * y0.z + w1 * y1.z;
    o.w = w0 * y0.w + w1 * y1.w;
    *(float4*)(out + (size_t)t * DIM + d) = o;
}

// ---------------------------------------------------------------- launch
extern "C" void kernel_launch(void* const* d_in, const int* in_sizes, int n_in,
                              void* d_out, int out_size) {
    const float* x  = (const float*)d_in[0];
    const float* Wr = (const float*)d_in[1];
    const float* W1 = (const float*)d_in[2];
    const float* b1 = (const float*)d_in[3];
    const float* W2 = (const float*)d_in[4];
    const float* b2 = (const float*)d_in[5];
    float* out = (float*)d_out;
    (void)in_sizes; (void)n_in; (void)out_size;

    zero_cnt_kernel<<<1, 32>>>();
    router_kernel<<<TOKENS, 256>>>(x, Wr);
    fc1_kernel<<<dim3(TOKENS / 128, HID / 128, NUM_E), 256>>>(x, W1, b1);
    fc2_kernel<<<dim3(TOKENS / 128, DIM / 128, NUM_E), 256>>>(W2, b2);
    combine_kernel<<<TOKENS, 256>>>(out);
}